// round 3
// baseline (speedup 1.0000x reference)
#include <cuda_runtime.h>

// B=16, Wn=64, K=256, E=128, O=64
// x(16,64,256), lin_w(128,128), lin_b(128), a(128), bias_kk(256,256),
// fc_w(64,256), fc_b(64) -> out(16,64,64) fp32

typedef unsigned long long ull;

__device__ __forceinline__ ull f2_add(ull a, ull b) {
    ull r; asm("add.rn.f32x2 %0,%1,%2;" : "=l"(r) : "l"(a), "l"(b)); return r;
}
__device__ __forceinline__ ull f2_fma(ull a, ull b, ull c) {
    ull r; asm("fma.rn.f32x2 %0,%1,%2,%3;" : "=l"(r) : "l"(a), "l"(b), "l"(c)); return r;
}
__device__ __forceinline__ float f2_hadd(ull a) {
    float lo, hi; asm("mov.b64 {%0,%1},%2;" : "=f"(lo), "=f"(hi) : "l"(a)); return lo + hi;
}
__device__ __forceinline__ ull f2_dup(float v) {
    ull r; asm("mov.b64 %0,{%1,%1};" : "=l"(r) : "f"(v)); return r;
}
__device__ __forceinline__ void f2_unpack(ull a, float& lo, float& hi) {
    asm("mov.b64 {%0,%1},%2;" : "=f"(lo), "=f"(hi) : "l"(a));
}

// Scratch (device globals)
__device__ float g_L[16 * 256 * 128];
__device__ float g_R[16 * 256 * 128];
__device__ float g_sL[16 * 256];
__device__ float g_sR[16 * 256];
__device__ float g_h[16 * 256 * 64];

// ---------------------------------------------------------------------------
// k1: GEMM C[4096,256] = A[4096,64] x W[256,64]^T
//   A[b*256+k][w] = x[b,w,k];  W row n: lin_w[(n&127)][ (n>>7)*64 + w ]
//   n<128 -> g_L (+lin_b), n>=128 -> g_R
// grid = 64 mtiles x 4 ntiles = 256 blocks, 128 threads, thread tile 8m x 4n
// ---------------------------------------------------------------------------
__global__ void __launch_bounds__(128, 4)
k1_lr(const float* __restrict__ x, const float* __restrict__ lin_w,
      const float* __restrict__ lin_b) {
    __shared__ float As[64 * 68];   // As[w][m]
    __shared__ float Ws[64 * 68];   // Ws[w][n]

    int bx = blockIdx.x;
    int mt = bx >> 2, nt = bx & 3;
    int b = mt >> 2, k0 = (mt & 3) * 64;
    int half = nt >> 1, e0 = (nt & 1) * 64;
    int tid = threadIdx.x;

    // stage A (transpose x tile): 1024 float4
#pragma unroll
    for (int t = 0; t < 8; t++) {
        int idx = t * 128 + tid;
        int w = idx >> 4, m4 = idx & 15;
        float4 v = *reinterpret_cast<const float4*>(x + b * 16384 + w * 256 + k0 + m4 * 4);
        *reinterpret_cast<float4*>(&As[w * 68 + m4 * 4]) = v;
    }
    // stage W (transpose lin_w tile): 1024 float4
#pragma unroll
    for (int t = 0; t < 8; t++) {
        int idx = t * 128 + tid;
        int n = idx >> 4, w4 = idx & 15;
        float4 v = *reinterpret_cast<const float4*>(lin_w + (e0 + n) * 128 + half * 64 + w4 * 4);
        Ws[(w4 * 4 + 0) * 68 + n] = v.x;
        Ws[(w4 * 4 + 1) * 68 + n] = v.y;
        Ws[(w4 * 4 + 2) * 68 + n] = v.z;
        Ws[(w4 * 4 + 3) * 68 + n] = v.w;
    }
    __syncthreads();

    int mg = tid >> 4, ng = tid & 15;   // m = mg*8.., n = ng*4..
    ull acc[4][4];                      // [n][mpair]
#pragma unroll
    for (int n = 0; n < 4; n++)
#pragma unroll
        for (int p = 0; p < 4; p++) acc[n][p] = 0ULL;

#pragma unroll 8
    for (int w = 0; w < 64; w++) {
        const ull* ap = reinterpret_cast<const ull*>(&As[w * 68 + mg * 8]);
        ull a0 = ap[0], a1 = ap[1], a2 = ap[2], a3 = ap[3];
        float4 wn = *reinterpret_cast<const float4*>(&Ws[w * 68 + ng * 4]);
        ull w0 = f2_dup(wn.x), w1 = f2_dup(wn.y), w2 = f2_dup(wn.z), w3 = f2_dup(wn.w);
        acc[0][0] = f2_fma(a0, w0, acc[0][0]); acc[0][1] = f2_fma(a1, w0, acc[0][1]);
        acc[0][2] = f2_fma(a2, w0, acc[0][2]); acc[0][3] = f2_fma(a3, w0, acc[0][3]);
        acc[1][0] = f2_fma(a0, w1, acc[1][0]); acc[1][1] = f2_fma(a1, w1, acc[1][1]);
        acc[1][2] = f2_fma(a2, w1, acc[1][2]); acc[1][3] = f2_fma(a3, w1, acc[1][3]);
        acc[2][0] = f2_fma(a0, w2, acc[2][0]); acc[2][1] = f2_fma(a1, w2, acc[2][1]);
        acc[2][2] = f2_fma(a2, w2, acc[2][2]); acc[2][3] = f2_fma(a3, w2, acc[2][3]);
        acc[3][0] = f2_fma(a0, w3, acc[3][0]); acc[3][1] = f2_fma(a1, w3, acc[3][1]);
        acc[3][2] = f2_fma(a2, w3, acc[3][2]); acc[3][3] = f2_fma(a3, w3, acc[3][3]);
    }

    float4 lb4 = make_float4(0.f, 0.f, 0.f, 0.f);
    if (half == 0) lb4 = *reinterpret_cast<const float4*>(lin_b + e0 + ng * 4);
    float* outbase = (half ? g_R : g_L) + (b * 256 + k0 + mg * 8) * 128 + e0 + ng * 4;
#pragma unroll
    for (int p = 0; p < 4; p++) {
        float lo[4], hi[4];
#pragma unroll
        for (int n = 0; n < 4; n++) f2_unpack(acc[n][p], lo[n], hi[n]);
        *reinterpret_cast<float4*>(outbase + (2 * p) * 128) =
            make_float4(lo[0] + lb4.x, lo[1] + lb4.y, lo[2] + lb4.z, lo[3] + lb4.w);
        *reinterpret_cast<float4*>(outbase + (2 * p + 1) * 128) =
            make_float4(hi[0] + lb4.x, hi[1] + lb4.y, hi[2] + lb4.z, hi[3] + lb4.w);
    }
}

// ---------------------------------------------------------------------------
// k1b: sL[row] = 0.6 * sum_e a_e L[row,e]; sR likewise.
// grid = 256 blocks (16 rows each), 128 threads (8 threads per row)
// ---------------------------------------------------------------------------
__global__ void __launch_bounds__(128, 8)
k1b_s(const float* __restrict__ a) {
    __shared__ float as[128];
    int tid = threadIdx.x;
    as[tid] = a[tid];
    __syncthreads();

    int row = blockIdx.x * 16 + (tid >> 3);
    int g = tid & 7;
    const float4* Lp = reinterpret_cast<const float4*>(g_L + row * 128 + g * 16);
    const float4* Rp = reinterpret_cast<const float4*>(g_R + row * 128 + g * 16);
    const float4* Ap = reinterpret_cast<const float4*>(as) + g * 4;
    float sl = 0.f, sr = 0.f;
#pragma unroll
    for (int u = 0; u < 4; u++) {
        float4 lv = Lp[u], rv = Rp[u], av = Ap[u];
        sl += lv.x * av.x + lv.y * av.y + lv.z * av.z + lv.w * av.w;
        sr += rv.x * av.x + rv.y * av.y + rv.z * av.z + rv.w * av.w;
    }
#pragma unroll
    for (int o = 4; o > 0; o >>= 1) {
        sl += __shfl_down_sync(0xffffffffu, sl, o, 8);
        sr += __shfl_down_sync(0xffffffffu, sr, o, 8);
    }
    if (g == 0) {
        g_sL[row] = 0.6f * sl;
        g_sR[row] = 0.6f * sr;
    }
}

// ---------------------------------------------------------------------------
// k2: e = sL_i + sR_j + sum_e (0.4 a_e)|L+R| + bias_kk; softmax_j; h=sigmoid(p@v)
// grid = 16b x 8 itiles = 128 blocks, 256 threads, TI=32, TJ=64 (4 j-tiles)
// dynamic smem 85,248 bytes
// ---------------------------------------------------------------------------
__global__ void __launch_bounds__(256, 1)
k2_attn(const float* __restrict__ x, const float* __restrict__ bias_kk,
        const float* __restrict__ a) {
    extern __shared__ float S[];
    const int LS = 0;        // 32 x 132
    const int RS = 4224;     // 64 x 130 (reused as h partials 4x32x64)
    const int ES = 12544;    // 32 x 260
    const int CS = 20864;    // 128
    const int SRS = 20992;   // 256
    const int SLS = 21248;   // 32
    const int INVS = 21280;  // 32
    const ull ABSM = 0x7FFFFFFF7FFFFFFFULL;

    int tid = threadIdx.x;
    int b = blockIdx.x >> 3;
    int i0 = (blockIdx.x & 7) << 5;

    // stage L (32x128), scalars
    const float* Lg = g_L + (b * 256 + i0) * 128;
#pragma unroll
    for (int t = 0; t < 4; t++) {
        int idx = t * 256 + tid;
        int row = idx >> 5, c4 = idx & 31;
        float4 v = *reinterpret_cast<const float4*>(Lg + row * 128 + c4 * 4);
        *reinterpret_cast<float4*>(&S[LS + row * 132 + c4 * 4]) = v;
    }
    if (tid < 128) S[CS + tid] = 0.4f * a[tid];
    S[SRS + tid] = g_sR[b * 256 + tid];
    if (tid < 32) S[SLS + tid] = g_sL[b * 256 + i0 + tid];

    int ig = tid >> 5;   // 0..7  -> i = ig + 8u
    int jg = tid & 15;   // 0..15 -> j = jt*64 + jg + 16v
    const ull* Lp0 = reinterpret_cast<const ull*>(&S[LS + (ig) * 132]);
    const ull* Lp1 = reinterpret_cast<const ull*>(&S[LS + (ig + 8) * 132]);
    const ull* Lp2 = reinterpret_cast<const ull*>(&S[LS + (ig + 16) * 132]);
    const ull* Lp3 = reinterpret_cast<const ull*>(&S[LS + (ig + 24) * 132]);
    const ull* Cp = reinterpret_cast<const ull*>(&S[CS]);

    for (int jt = 0; jt < 4; jt++) {
        __syncthreads();
        const float* Rg = g_R + (b * 256 + jt * 64) * 128;
#pragma unroll
        for (int t = 0; t < 8; t++) {
            int idx = t * 256 + tid;
            int row = idx >> 5, c4 = idx & 31;
            float4 v = *reinterpret_cast<const float4*>(Rg + row * 128 + c4 * 4);
            float* d = &S[RS + row * 130 + c4 * 4];
            *reinterpret_cast<float2*>(d) = make_float2(v.x, v.y);
            *reinterpret_cast<float2*>(d + 2) = make_float2(v.z, v.w);
        }
        __syncthreads();

        const ull* Rp0 = reinterpret_cast<const ull*>(&S[RS + (jg) * 130]);
        const ull* Rp1 = reinterpret_cast<const ull*>(&S[RS + (jg + 16) * 130]);
        const ull* Rp2 = reinterpret_cast<const ull*>(&S[RS + (jg + 32) * 130]);
        const ull* Rp3 = reinterpret_cast<const ull*>(&S[RS + (jg + 48) * 130]);

        ull acc[4][4];
#pragma unroll
        for (int u = 0; u < 4; u++)
#pragma unroll
            for (int v = 0; v < 4; v++) acc[u][v] = 0ULL;

#pragma unroll 4
        for (int ep = 0; ep < 64; ep++) {
            ull c = Cp[ep];
            ull l0 = Lp0[ep], l1 = Lp1[ep], l2 = Lp2[ep], l3 = Lp3[ep];
            ull r0 = Rp0[ep], r1 = Rp1[ep], r2 = Rp2[ep], r3 = Rp3[ep];
            acc[0][0] = f2_fma(f2_add(l0, r0) & ABSM, c, acc[0][0]);
            acc[0][1] = f2_fma(f2_add(l0, r1) & ABSM, c, acc[0][1]);
            acc[0][2] = f2_fma(f2_add(l0, r2) & ABSM, c, acc[0][2]);
            acc[0][3] = f2_fma(f2_add(l0, r3) & ABSM, c, acc[0][3]);
            acc[1][0] = f2_fma(f2_add(l1, r0) & ABSM, c, acc[1][0]);
            acc[1][1] = f2_fma(f2_add(l1, r1) & ABSM, c, acc[1][1]);
            acc[1][2] = f2_fma(f2_add(l1, r2) & ABSM, c, acc[1][2]);
            acc[1][3] = f2_fma(f2_add(l1, r3) & ABSM, c, acc[1][3]);
            acc[2][0] = f2_fma(f2_add(l2, r0) & ABSM, c, acc[2][0]);
            acc[2][1] = f2_fma(f2_add(l2, r1) & ABSM, c, acc[2][1]);
            acc[2][2] = f2_fma(f2_add(l2, r2) & ABSM, c, acc[2][2]);
            acc[2][3] = f2_fma(f2_add(l2, r3) & ABSM, c, acc[2][3]);
            acc[3][0] = f2_fma(f2_add(l3, r0) & ABSM, c, acc[3][0]);
            acc[3][1] = f2_fma(f2_add(l3, r1) & ABSM, c, acc[3][1]);
            acc[3][2] = f2_fma(f2_add(l3, r2) & ABSM, c, acc[3][2]);
            acc[3][3] = f2_fma(f2_add(l3, r3) & ABSM, c, acc[3][3]);
        }
#pragma unroll
        for (int u = 0; u < 4; u++) {
            int i = ig + 8 * u;
            float sl = S[SLS + i];
#pragma unroll
            for (int v = 0; v < 4; v++) {
                int j = jt * 64 + jg + 16 * v;
                S[ES + i * 260 + j] =
                    f2_hadd(acc[u][v]) + sl + S[SRS + j] + bias_kk[(i0 + i) * 256 + j];
            }
        }
    }
    __syncthreads();

    // softmax over j: 8 warps x 4 rows
    int wid = tid >> 5, lane = tid & 31;
#pragma unroll
    for (int s = 0; s < 4; s++) {
        int r = wid * 4 + s;
        float v[8];
        float m = -1e30f;
#pragma unroll
        for (int u = 0; u < 8; u++) {
            v[u] = S[ES + r * 260 + u * 32 + lane];
            m = fmaxf(m, v[u]);
        }
#pragma unroll
        for (int o = 16; o > 0; o >>= 1) m = fmaxf(m, __shfl_xor_sync(0xffffffffu, m, o));
        float sum = 0.f;
#pragma unroll
        for (int u = 0; u < 8; u++) {
            float p = __expf(v[u] - m);
            S[ES + r * 260 + u * 32 + lane] = p;
            sum += p;
        }
#pragma unroll
        for (int o = 16; o > 0; o >>= 1) sum += __shfl_xor_sync(0xffffffffu, sum, o);
        if (lane == 0) S[INVS + r] = 1.f / sum;
    }
    __syncthreads();

    // h: h[b,i,w] = sigmoid(inv_i * sum_j p_ij x[b,w,j]); thread: 1 w, 32 i, 64 j
    int w = tid & 63, q = tid >> 6;
    ull f[32];
#pragma unroll
    for (int ii = 0; ii < 32; ii++) f[ii] = 0ULL;
    const float* xp = x + b * 16384 + w * 256;
    for (int j4 = q * 16; j4 < q * 16 + 16; j4++) {
        ulonglong2 xq = *reinterpret_cast<const ulonglong2*>(xp + j4 * 4);
#pragma unroll
        for (int ii = 0; ii < 32; ii++) {
            ulonglong2 pq = *reinterpret_cast<const ulonglong2*>(&S[ES + ii * 260 + j4 * 4]);
            f[ii] = f2_fma(xq.x, pq.x, f[ii]);
            f[ii] = f2_fma(xq.y, pq.y, f[ii]);
        }
    }
#pragma unroll
    for (int ii = 0; ii < 32; ii++)
        S[RS + q * 2048 + ii * 64 + w] = f2_hadd(f[ii]);
    __syncthreads();

#pragma unroll
    for (int t = 0; t < 8; t++) {
        int idx = t * 256 + tid;
        int ii = idx >> 6, w2 = idx & 63;
        float sum = S[RS + ii * 64 + w2] + S[RS + 2048 + ii * 64 + w2] +
                    S[RS + 4096 + ii * 64 + w2] + S[RS + 6144 + ii * 64 + w2];
        float val = sum * S[INVS + ii];
        g_h[(b * 256 + i0 + ii) * 64 + w2] = 1.f / (1.f + __expf(-val));
    }
}

// ---------------------------------------------------------------------------
// k3: out[b,w,o] = sum_k h[b,k,w] * fc_w[o,k] + fc_b[o]
// grid = 64 blocks, 256 threads, packed over k pairs
// ---------------------------------------------------------------------------
__global__ void __launch_bounds__(256, 2)
k3_fc(const float* __restrict__ fc_w, const float* __restrict__ fc_b,
      float* __restrict__ out) {
    __shared__ float hsT[16 * 130];
    __shared__ float fws[64 * 130];

    int bx = blockIdx.x;
    int b = bx >> 2, wq = bx & 3;
    int w0 = wq * 16;
    int tid = threadIdx.x;
    int w16 = tid & 15, og = tid >> 4;

    ull acc[4] = {0ULL, 0ULL, 0ULL, 0ULL};
    for (int kc = 0; kc < 2; kc++) {
        int k0c = kc * 128;
        __syncthreads();
#pragma unroll
        for (int t = 0; t < 8; t++) {
            int idx = t * 256 + tid;
            int kk = idx >> 4, ww = idx & 15;
            hsT[ww * 130 + kk] = g_h[(b * 256 + k0c + kk) * 64 + w0 + ww];
        }
#pragma unroll
        for (int t = 0; t < 8; t++) {
            int idx = t * 256 + tid;
            int row = idx >> 5, c4 = idx & 31;
            float4 v = *reinterpret_cast<const float4*>(fc_w + row * 256 + k0c + c4 * 4);
            float* d = &fws[row * 130 + c4 * 4];
            *reinterpret_cast<float2*>(d) = make_float2(v.x, v.y);
            *reinterpret_cast<float2*>(d + 2) = make_float2(v.z, v.w);
        }
        __syncthreads();

        const ull* hp = reinterpret_cast<const ull*>(&hsT[w16 * 130]);
#pragma unroll 8
        for (int kp = 0; kp < 64; kp++) {
            ull h2 = hp[kp];
#pragma unroll
            for (int m = 0; m < 4; m++)
                acc[m] = f2_fma(h2,
                    *reinterpret_cast<const ull*>(&fws[(og + 16 * m) * 130 + kp * 2]),
                    acc[m]);
        }
    }
#pragma unroll
    for (int m = 0; m < 4; m++) {
        int o = og + 16 * m;
        out[(b * 64 + w0 + w16) * 64 + o] = f2_hadd(acc[m]) + fc_b[o];
    }
}

// ---------------------------------------------------------------------------
extern "C" void kernel_launch(void* const* d_in, const int* in_sizes, int n_in,
                              void* d_out, int out_size) {
    const float* x       = (const float*)d_in[0];
    const float* lin_w   = (const float*)d_in[1];
    const float* lin_b   = (const float*)d_in[2];
    const float* a       = (const float*)d_in[3];
    const float* bias_kk = (const float*)d_in[4];
    const float* fc_w    = (const float*)d_in[5];
    const float* fc_b    = (const float*)d_in[6];
    float* out = (float*)d_out;

    cudaFuncSetAttribute(k2_attn, cudaFuncAttributeMaxDynamicSharedMemorySize, 87040);

    k1_lr<<<256, 128>>>(x, lin_w, lin_b);
    k1b_s<<<256, 128>>>(a);
    k2_attn<<<128, 256, 85248>>>(x, bias_kk, a);
    k3_fc<<<64, 256>>>(fc_w, fc_b, out);
}

// round 4
// speedup vs baseline: 1.2636x; 1.2636x over previous
#include <cuda_runtime.h>

// B=16, Wn=64, K=256, E=128, O=64

typedef unsigned long long ull;

__device__ __forceinline__ ull f2_add(ull a, ull b) {
    ull r; asm("add.rn.f32x2 %0,%1,%2;" : "=l"(r) : "l"(a), "l"(b)); return r;
}
__device__ __forceinline__ ull f2_fma(ull a, ull b, ull c) {
    ull r; asm("fma.rn.f32x2 %0,%1,%2,%3;" : "=l"(r) : "l"(a), "l"(b), "l"(c)); return r;
}
__device__ __forceinline__ float f2_hadd(ull a) {
    float lo, hi; asm("mov.b64 {%0,%1},%2;" : "=f"(lo), "=f"(hi) : "l"(a)); return lo + hi;
}
__device__ __forceinline__ ull f2_dup(float v) {
    ull r; asm("mov.b64 %0,{%1,%1};" : "=l"(r) : "f"(v)); return r;
}
__device__ __forceinline__ void f2_unpack(ull a, float& lo, float& hi) {
    asm("mov.b64 {%0,%1},%2;" : "=f"(lo), "=f"(hi) : "l"(a));
}

// Scratch
__device__ float g_L[16 * 256 * 128];
__device__ float g_R[16 * 256 * 128];
__device__ float g_sL[16 * 256];
__device__ float g_sR[16 * 256];
__device__ float g_h[16 * 256 * 64];

// ---------------------------------------------------------------------------
// k1: C[4096,256] = A[4096,64] x W[256,64]^T ; outer-product, 8m x 4n tiles
// grid = 256 blocks, 128 threads
// ---------------------------------------------------------------------------
__global__ void __launch_bounds__(128, 4)
k1_lr(const float* __restrict__ x, const float* __restrict__ lin_w,
      const float* __restrict__ lin_b) {
    __shared__ float As[64 * 68];
    __shared__ float Ws[64 * 68];

    int bx = blockIdx.x;
    int mt = bx >> 2, nt = bx & 3;
    int b = mt >> 2, k0 = (mt & 3) * 64;
    int half = nt >> 1, e0 = (nt & 1) * 64;
    int tid = threadIdx.x;

#pragma unroll
    for (int t = 0; t < 8; t++) {
        int idx = t * 128 + tid;
        int w = idx >> 4, m4 = idx & 15;
        float4 v = *reinterpret_cast<const float4*>(x + b * 16384 + w * 256 + k0 + m4 * 4);
        *reinterpret_cast<float4*>(&As[w * 68 + m4 * 4]) = v;
    }
#pragma unroll
    for (int t = 0; t < 8; t++) {
        int idx = t * 128 + tid;
        int n = idx >> 4, w4 = idx & 15;
        float4 v = *reinterpret_cast<const float4*>(lin_w + (e0 + n) * 128 + half * 64 + w4 * 4);
        Ws[(w4 * 4 + 0) * 68 + n] = v.x;
        Ws[(w4 * 4 + 1) * 68 + n] = v.y;
        Ws[(w4 * 4 + 2) * 68 + n] = v.z;
        Ws[(w4 * 4 + 3) * 68 + n] = v.w;
    }
    __syncthreads();

    int mg = tid >> 4, ng = tid & 15;
    ull acc[4][4];
#pragma unroll
    for (int n = 0; n < 4; n++)
#pragma unroll
        for (int p = 0; p < 4; p++) acc[n][p] = 0ULL;

#pragma unroll 8
    for (int w = 0; w < 64; w++) {
        const ull* ap = reinterpret_cast<const ull*>(&As[w * 68 + mg * 8]);
        ull a0 = ap[0], a1 = ap[1], a2 = ap[2], a3 = ap[3];
        float4 wn = *reinterpret_cast<const float4*>(&Ws[w * 68 + ng * 4]);
        ull w0 = f2_dup(wn.x), w1 = f2_dup(wn.y), w2 = f2_dup(wn.z), w3 = f2_dup(wn.w);
        acc[0][0] = f2_fma(a0, w0, acc[0][0]); acc[0][1] = f2_fma(a1, w0, acc[0][1]);
        acc[0][2] = f2_fma(a2, w0, acc[0][2]); acc[0][3] = f2_fma(a3, w0, acc[0][3]);
        acc[1][0] = f2_fma(a0, w1, acc[1][0]); acc[1][1] = f2_fma(a1, w1, acc[1][1]);
        acc[1][2] = f2_fma(a2, w1, acc[1][2]); acc[1][3] = f2_fma(a3, w1, acc[1][3]);
        acc[2][0] = f2_fma(a0, w2, acc[2][0]); acc[2][1] = f2_fma(a1, w2, acc[2][1]);
        acc[2][2] = f2_fma(a2, w2, acc[2][2]); acc[2][3] = f2_fma(a3, w2, acc[2][3]);
        acc[3][0] = f2_fma(a0, w3, acc[3][0]); acc[3][1] = f2_fma(a1, w3, acc[3][1]);
        acc[3][2] = f2_fma(a2, w3, acc[3][2]); acc[3][3] = f2_fma(a3, w3, acc[3][3]);
    }

    float4 lb4 = make_float4(0.f, 0.f, 0.f, 0.f);
    if (half == 0) lb4 = *reinterpret_cast<const float4*>(lin_b + e0 + ng * 4);
    float* outbase = (half ? g_R : g_L) + (b * 256 + k0 + mg * 8) * 128 + e0 + ng * 4;
#pragma unroll
    for (int p = 0; p < 4; p++) {
        float lo[4], hi[4];
#pragma unroll
        for (int n = 0; n < 4; n++) f2_unpack(acc[n][p], lo[n], hi[n]);
        *reinterpret_cast<float4*>(outbase + (2 * p) * 128) =
            make_float4(lo[0] + lb4.x, lo[1] + lb4.y, lo[2] + lb4.z, lo[3] + lb4.w);
        *reinterpret_cast<float4*>(outbase + (2 * p + 1) * 128) =
            make_float4(hi[0] + lb4.x, hi[1] + lb4.y, hi[2] + lb4.z, hi[3] + lb4.w);
    }
}

// ---------------------------------------------------------------------------
// k1b: sL/sR row dots. grid = 256 blocks x 128 thr (8 thr per row)
// ---------------------------------------------------------------------------
__global__ void __launch_bounds__(128, 8)
k1b_s(const float* __restrict__ a) {
    __shared__ float as[128];
    int tid = threadIdx.x;
    as[tid] = a[tid];
    __syncthreads();

    int row = blockIdx.x * 16 + (tid >> 3);
    int g = tid & 7;
    const float4* Lp = reinterpret_cast<const float4*>(g_L + row * 128 + g * 16);
    const float4* Rp = reinterpret_cast<const float4*>(g_R + row * 128 + g * 16);
    const float4* Ap = reinterpret_cast<const float4*>(as) + g * 4;
    float sl = 0.f, sr = 0.f;
#pragma unroll
    for (int u = 0; u < 4; u++) {
        float4 lv = Lp[u], rv = Rp[u], av = Ap[u];
        sl += lv.x * av.x + lv.y * av.y + lv.z * av.z + lv.w * av.w;
        sr += rv.x * av.x + rv.y * av.y + rv.z * av.z + rv.w * av.w;
    }
#pragma unroll
    for (int o = 4; o > 0; o >>= 1) {
        sl += __shfl_down_sync(0xffffffffu, sl, o, 8);
        sr += __shfl_down_sync(0xffffffffu, sr, o, 8);
    }
    if (g == 0) {
        g_sL[row] = 0.6f * sl;
        g_sR[row] = 0.6f * sr;
    }
}

// ---------------------------------------------------------------------------
// k2: fused e-scores + softmax + h. grid = 128 blocks (16b x 8 itiles),
// 256 thr. e-phase: 128 (ig x jg) slots x 2 e-halves; 4i x 4j register tiles.
// dynamic smem 118,528 B
// ---------------------------------------------------------------------------
__global__ void __launch_bounds__(256, 1)
k2_attn(const float* __restrict__ x, const float* __restrict__ bias_kk,
        const float* __restrict__ a) {
    extern __shared__ float S[];
    const int LS = 0;        // 32 x 132
    const int RS = 4224;     // 64 x 130  (reused as h partials 2x32x64)
    const int ES = 12544;    // 32 x 260  (eh=0 partials, then probabilities)
    const int ES2 = 20864;   // 32 x 260  (eh=1 partials + linear terms)
    const int CS = 29184;    // 128
    const int SRS = 29312;   // 256
    const int SLS = 29568;   // 32
    const int INVS = 29600;  // 32
    const ull ABSM = 0x7FFFFFFF7FFFFFFFULL;

    int tid = threadIdx.x;
    int b = blockIdx.x >> 3;
    int i0 = (blockIdx.x & 7) << 5;

    const float* Lg = g_L + (b * 256 + i0) * 128;
#pragma unroll
    for (int t = 0; t < 4; t++) {
        int idx = t * 256 + tid;
        int row = idx >> 5, c4 = idx & 31;
        float4 v = *reinterpret_cast<const float4*>(Lg + row * 128 + c4 * 4);
        *reinterpret_cast<float4*>(&S[LS + row * 132 + c4 * 4]) = v;
    }
    if (tid < 128) S[CS + tid] = 0.4f * a[tid];
    S[SRS + tid] = g_sR[b * 256 + tid];
    if (tid < 32) S[SLS + tid] = g_sL[b * 256 + i0 + tid];

    int eh = tid >> 7;          // e-half
    int r = tid & 127;
    int ig = r >> 4;            // 0..7 -> i = ig + 8u
    int jg = r & 15;            // 0..15 -> j = jt*64 + jg + 16v
    const ull* Lp0 = reinterpret_cast<const ull*>(&S[LS + (ig) * 132]) + eh * 32;
    const ull* Lp1 = reinterpret_cast<const ull*>(&S[LS + (ig + 8) * 132]) + eh * 32;
    const ull* Lp2 = reinterpret_cast<const ull*>(&S[LS + (ig + 16) * 132]) + eh * 32;
    const ull* Lp3 = reinterpret_cast<const ull*>(&S[LS + (ig + 24) * 132]) + eh * 32;
    const ull* Cp = reinterpret_cast<const ull*>(&S[CS]) + eh * 32;

    for (int jt = 0; jt < 4; jt++) {
        __syncthreads();
        const float* Rg = g_R + (b * 256 + jt * 64) * 128;
#pragma unroll
        for (int t = 0; t < 8; t++) {
            int idx = t * 256 + tid;
            int row = idx >> 5, c4 = idx & 31;
            float4 v = *reinterpret_cast<const float4*>(Rg + row * 128 + c4 * 4);
            float* d = &S[RS + row * 130 + c4 * 4];
            *reinterpret_cast<float2*>(d) = make_float2(v.x, v.y);
            *reinterpret_cast<float2*>(d + 2) = make_float2(v.z, v.w);
        }
        __syncthreads();

        const ull* Rp0 = reinterpret_cast<const ull*>(&S[RS + (jg) * 130]) + eh * 32;
        const ull* Rp1 = reinterpret_cast<const ull*>(&S[RS + (jg + 16) * 130]) + eh * 32;
        const ull* Rp2 = reinterpret_cast<const ull*>(&S[RS + (jg + 32) * 130]) + eh * 32;
        const ull* Rp3 = reinterpret_cast<const ull*>(&S[RS + (jg + 48) * 130]) + eh * 32;

        ull acc[4][4];
#pragma unroll
        for (int u = 0; u < 4; u++)
#pragma unroll
            for (int v = 0; v < 4; v++) acc[u][v] = 0ULL;

#pragma unroll 4
        for (int ep = 0; ep < 32; ep++) {
            ull c = Cp[ep];
            ull l0 = Lp0[ep], l1 = Lp1[ep], l2 = Lp2[ep], l3 = Lp3[ep];
            ull r0 = Rp0[ep], r1 = Rp1[ep], r2 = Rp2[ep], r3 = Rp3[ep];
            acc[0][0] = f2_fma(f2_add(l0, r0) & ABSM, c, acc[0][0]);
            acc[0][1] = f2_fma(f2_add(l0, r1) & ABSM, c, acc[0][1]);
            acc[0][2] = f2_fma(f2_add(l0, r2) & ABSM, c, acc[0][2]);
            acc[0][3] = f2_fma(f2_add(l0, r3) & ABSM, c, acc[0][3]);
            acc[1][0] = f2_fma(f2_add(l1, r0) & ABSM, c, acc[1][0]);
            acc[1][1] = f2_fma(f2_add(l1, r1) & ABSM, c, acc[1][1]);
            acc[1][2] = f2_fma(f2_add(l1, r2) & ABSM, c, acc[1][2]);
            acc[1][3] = f2_fma(f2_add(l1, r3) & ABSM, c, acc[1][3]);
            acc[2][0] = f2_fma(f2_add(l2, r0) & ABSM, c, acc[2][0]);
            acc[2][1] = f2_fma(f2_add(l2, r1) & ABSM, c, acc[2][1]);
            acc[2][2] = f2_fma(f2_add(l2, r2) & ABSM, c, acc[2][2]);
            acc[2][3] = f2_fma(f2_add(l2, r3) & ABSM, c, acc[2][3]);
            acc[3][0] = f2_fma(f2_add(l3, r0) & ABSM, c, acc[3][0]);
            acc[3][1] = f2_fma(f2_add(l3, r1) & ABSM, c, acc[3][1]);
            acc[3][2] = f2_fma(f2_add(l3, r2) & ABSM, c, acc[3][2]);
            acc[3][3] = f2_fma(f2_add(l3, r3) & ABSM, c, acc[3][3]);
        }
        if (eh == 0) {
#pragma unroll
            for (int u = 0; u < 4; u++) {
                int i = ig + 8 * u;
#pragma unroll
                for (int v = 0; v < 4; v++) {
                    int j = jt * 64 + jg + 16 * v;
                    S[ES + i * 260 + j] = f2_hadd(acc[u][v]);
                }
            }
        } else {
#pragma unroll
            for (int u = 0; u < 4; u++) {
                int i = ig + 8 * u;
                float sl = S[SLS + i];
#pragma unroll
                for (int v = 0; v < 4; v++) {
                    int j = jt * 64 + jg + 16 * v;
                    S[ES2 + i * 260 + j] =
                        f2_hadd(acc[u][v]) + sl + S[SRS + j] + bias_kk[(i0 + i) * 256 + j];
                }
            }
        }
    }
    __syncthreads();

    // softmax over j: 8 warps x 4 rows (combine ES + ES2)
    int wid = tid >> 5, lane = tid & 31;
#pragma unroll
    for (int s = 0; s < 4; s++) {
        int rr = wid * 4 + s;
        float v[8];
        float m = -1e30f;
#pragma unroll
        for (int u = 0; u < 8; u++) {
            int c = u * 32 + lane;
            v[u] = S[ES + rr * 260 + c] + S[ES2 + rr * 260 + c];
            m = fmaxf(m, v[u]);
        }
#pragma unroll
        for (int o = 16; o > 0; o >>= 1) m = fmaxf(m, __shfl_xor_sync(0xffffffffu, m, o));
        float sum = 0.f;
#pragma unroll
        for (int u = 0; u < 8; u++) {
            float p = __expf(v[u] - m);
            S[ES + rr * 260 + u * 32 + lane] = p;
            sum += p;
        }
#pragma unroll
        for (int o = 16; o > 0; o >>= 1) sum += __shfl_xor_sync(0xffffffffu, sum, o);
        if (lane == 0) S[INVS + rr] = 1.f / sum;
    }
    __syncthreads();

    // h: thread = (w in 64, q = j-half, ih = i-half); f[16] accumulators
    int w = tid & 63;
    int q = (tid >> 6) & 1;
    int ih = tid >> 7;
    ull f[16];
#pragma unroll
    for (int ii = 0; ii < 16; ii++) f[ii] = 0ULL;
    const float* xp = x + b * 16384 + w * 256 + q * 128;
    const float* pbase = &S[ES + (ih * 16) * 260 + q * 128];
    for (int j4 = 0; j4 < 32; j4++) {
        ulonglong2 xq = *reinterpret_cast<const ulonglong2*>(xp + j4 * 4);
#pragma unroll
        for (int ii = 0; ii < 16; ii++) {
            ulonglong2 pq = *reinterpret_cast<const ulonglong2*>(pbase + ii * 260 + j4 * 4);
            f[ii] = f2_fma(xq.x, pq.x, f[ii]);
            f[ii] = f2_fma(xq.y, pq.y, f[ii]);
        }
    }
#pragma unroll
    for (int ii = 0; ii < 16; ii++)
        S[RS + q * 2048 + (ih * 16 + ii) * 64 + w] = f2_hadd(f[ii]);
    __syncthreads();

#pragma unroll
    for (int t = 0; t < 8; t++) {
        int idx = t * 256 + tid;
        int ii = idx >> 6, w2 = idx & 63;
        float sum = S[RS + ii * 64 + w2] + S[RS + 2048 + ii * 64 + w2];
        float val = sum * S[INVS + ii];
        g_h[(b * 256 + i0 + ii) * 64 + w2] = 1.f / (1.f + __expf(-val));
    }
}

// ---------------------------------------------------------------------------
// k3: out[b,w,o] = sum_k h[b,k,w] fc_w[o,k] + fc_b[o]
// grid = 128 (16b x 8 wtiles of 8), 256 thr: w8 = tid&7, og = tid>>3 (o=og+32m)
// ---------------------------------------------------------------------------
__global__ void __launch_bounds__(256, 3)
k3_fc(const float* __restrict__ fc_w, const float* __restrict__ fc_b,
      float* __restrict__ out) {
    __shared__ float hsT[8 * 130];
    __shared__ float fws[64 * 130];

    int bx = blockIdx.x;
    int b = bx >> 3, wq = bx & 7;
    int w0 = wq * 8;
    int tid = threadIdx.x;
    int w8 = tid & 7, og = tid >> 3;   // og 0..31

    ull acc[2] = {0ULL, 0ULL};
    for (int kc = 0; kc < 2; kc++) {
        int k0c = kc * 128;
        __syncthreads();
#pragma unroll
        for (int t = 0; t < 4; t++) {
            int idx = t * 256 + tid;
            int kk = idx >> 3, ww = idx & 7;
            hsT[ww * 130 + kk] = g_h[(b * 256 + k0c + kk) * 64 + w0 + ww];
        }
#pragma unroll
        for (int t = 0; t < 8; t++) {
            int idx = t * 256 + tid;
            int row = idx >> 5, c4 = idx & 31;
            float4 v = *reinterpret_cast<const float4*>(fc_w + row * 256 + k0c + c4 * 4);
            float* d = &fws[row * 130 + c4 * 4];
            *reinterpret_cast<float2*>(d) = make_float2(v.x, v.y);
            *reinterpret_cast<float2*>(d + 2) = make_float2(v.z, v.w);
        }
        __syncthreads();

        const ull* hp = reinterpret_cast<const ull*>(&hsT[w8 * 130]);
        const ull* f0 = reinterpret_cast<const ull*>(&fws[og * 130]);
        const ull* f1 = reinterpret_cast<const ull*>(&fws[(og + 32) * 130]);
#pragma unroll 16
        for (int kp = 0; kp < 64; kp++) {
            ull h2 = hp[kp];
            acc[0] = f2_fma(h2, f0[kp], acc[0]);
            acc[1] = f2_fma(h2, f1[kp], acc[1]);
        }
    }
#pragma unroll
    for (int m = 0; m < 2; m++) {
        int o = og + 32 * m;
        out[(b * 64 + w0 + w8) * 64 + o] = f2_hadd(acc[m]) + fc_b[o];
    }
}

// ---------------------------------------------------------------------------
extern "C" void kernel_launch(void* const* d_in, const int* in_sizes, int n_in,
                              void* d_out, int out_size) {
    const float* x       = (const float*)d_in[0];
    const float* lin_w   = (const float*)d_in[1];
    const float* lin_b   = (const float*)d_in[2];
    const float* a       = (const float*)d_in[3];
    const float* bias_kk = (const float*)d_in[4];
    const float* fc_w    = (const float*)d_in[5];
    const float* fc_b    = (const float*)d_in[6];
    float* out = (float*)d_out;

    cudaFuncSetAttribute(k2_attn, cudaFuncAttributeMaxDynamicSharedMemorySize, 118528);

    k1_lr<<<256, 128>>>(x, lin_w, lin_b);
    k1b_s<<<256, 128>>>(a);
    k2_attn<<<128, 256, 118528>>>(x, bias_kk, a);
    k3_fc<<<128, 256>>>(fc_w, fc_b, out);
}